// round 16
// baseline (speedup 1.0000x reference)
#include <cuda_runtime.h>
#include <cuda_fp16.h>
#include <math.h>
#include <stdint.h>

#define B_    2
#define L_    1024
#define DIN   1024
#define DM    2048
#define DS    16
#define DR    128
#define KCONV 4
#define BL    (B_ * L_)
#define NPROJ 160
#define KSPLIT 8

// ---------------- scratch ----------------
__device__ __half g_xh[BL * DIN];            // fp16 x_in
__device__ __half g_xm_h[BL * DM];           // fp16 x = x_in @ W_in (conv input)
__device__ float  g_res[BL * DM];            // fp32 silu(x_in @ W_res)
__device__ float  g_xc[BL * DM];             // fp32 silu(conv(x)) (scan)
__device__ __half g_xch[BL * DM];            // fp16 copy (GEMM A)
__device__ float  g_projp[KSPLIT * BL * NPROJ];
__device__ float  g_proj[BL * NPROJ];
__device__ __half g_projh[BL * NPROJ];
__device__ float  g_delta[BL * DM];
__device__ __half g_yh[BL * DM];
__device__ __half g_Wth_inres[2 * DM * DIN];
__device__ __half g_Wth_out[DIN * DM];
__device__ __half g_Wth_cat[NPROJ * DM];
__device__ __half g_Wth_dtw[DM * DR];

// ---------------- helpers ----------------
__device__ __forceinline__ void mma_f16(float* c, const uint32_t* a, const uint32_t* b) {
    asm volatile(
        "mma.sync.aligned.m16n8k16.row.col.f32.f16.f16.f32 "
        "{%0,%1,%2,%3}, {%4,%5,%6,%7}, {%8,%9}, {%0,%1,%2,%3};"
        : "+f"(c[0]), "+f"(c[1]), "+f"(c[2]), "+f"(c[3])
        : "r"(a[0]), "r"(a[1]), "r"(a[2]), "r"(a[3]), "r"(b[0]), "r"(b[1]));
}
__device__ __forceinline__ void ldmx4(uint32_t* r, uint32_t addr) {
    asm volatile("ldmatrix.sync.aligned.m8n8.x4.shared.b16 {%0,%1,%2,%3}, [%4];"
        : "=r"(r[0]), "=r"(r[1]), "=r"(r[2]), "=r"(r[3]) : "r"(addr));
}
__device__ __forceinline__ void cpa16(uint32_t dst, const void* src) {
    asm volatile("cp.async.cg.shared.global [%0], [%1], 16;" :: "r"(dst), "l"(src));
}
__device__ __forceinline__ void cpa16z(uint32_t dst, const void* src, int srcbytes) {
    asm volatile("cp.async.cg.shared.global [%0], [%1], 16, %2;"
                 :: "r"(dst), "l"(src), "r"(srcbytes));
}
__device__ __forceinline__ void cpa_commit() { asm volatile("cp.async.commit_group;"); }
__device__ __forceinline__ void cpa_wait1()  { asm volatile("cp.async.wait_group 1;" ::: "memory"); }
__device__ __forceinline__ void cpa_wait0()  { asm volatile("cp.async.wait_group 0;" ::: "memory"); }

// ============ fp16 mma GEMM: MTxNT CTA tile, BK=64, NS-stage cp.async, ldmatrix ========
// C(M x N) = A(M x K) @ Bt(N x K)^T. Split-K via gridDim.z (kdiv slices, partials at
// C + z*pstride). SMEM rows: 128B, SW128 swizzle quad ^ (row&7).
// EPI: 0=plain fp32, 2=softplus(+bias) fp32, 4=dual: col<DM -> fp16 Hx, col>=DM -> silu fp32 C2
template<int MT, int NT, int NS, int EPI>
__global__ void __launch_bounds__(256, 2) gemm_h(
    const __half* __restrict__ A, int lda,
    const __half* __restrict__ Bt,
    float* __restrict__ C, float* __restrict__ C2, __half* __restrict__ Hx, int ldc,
    const float* __restrict__ bias, int N, int K,
    int kdiv, size_t pstride)
{
    constexpr int ABUF  = MT * 128;        // bytes per A stage (128B rows)
    constexpr int BBUF  = NT * 128;        // bytes per B stage
    constexpr int MI    = MT / 32;         // m-atoms per warp tile
    constexpr int NATOM = NT / 32;         // n-atoms per warp tile (warp n-width = NT/4)
    extern __shared__ char sh[];
    const uint32_t sA = (uint32_t)__cvta_generic_to_shared(sh);
    const uint32_t sB = sA + NS * ABUF;

    const int tid  = threadIdx.x;
    const int wid  = tid >> 5, lane = tid & 31;
    const int gid  = lane >> 2, tig = lane & 3;
    const int bm   = blockIdx.y * MT, bn = blockIdx.x * NT;
    const int wm   = (wid >> 2) * (MT / 2);
    const int wn   = (wid & 3) * (NT / 4);

    const int Keff = K / kdiv;
    const int koff = blockIdx.z * Keff;
    float* Cout = C + (size_t)blockIdx.z * pstride;

    float acc[MI][NATOM][4] = {};

    const int NC = Keff >> 6;              // 64-wide K chunks

    auto issue = [&](int c) {
        const int buf = c % NS;
        const int ko  = koff + c * 64;
        #pragma unroll
        for (int it = 0; it < MT * 8 / 256; ++it) {
            const int i = tid + it * 256;
            const int row = i >> 3, q = i & 7;
            const int sw = q ^ (row & 7);
            cpa16(sA + buf * ABUF + (uint32_t)(row * 128 + sw * 16),
                  A + (size_t)(bm + row) * lda + ko + q * 8);
        }
        #pragma unroll
        for (int it = 0; it < NT * 8 / 256; ++it) {
            const int i = tid + it * 256;
            const int row = i >> 3, q = i & 7;
            const int sw = q ^ (row & 7);
            const int brow = bn + row;
            cpa16z(sB + buf * BBUF + (uint32_t)(row * 128 + sw * 16),
                   Bt + (size_t)brow * K + ko + q * 8,
                   (brow < N) ? 16 : 0);
        }
        cpa_commit();
    };

    const int swl = lane & 7;
    const uint32_t aLm = sA + (uint32_t)((wm + (lane & 15)) * 128);
    const int aQ = lane >> 4;
    const uint32_t bLm = sB + (uint32_t)((wn + (lane & 7) + ((lane >> 4) & 1) * 8) * 128);
    const int bQ = (lane >> 3) & 1;

    auto compute = [&](int c) {
        const int buf = c % NS;
        const uint32_t Ab = aLm + buf * ABUF;
        const uint32_t Bb = bLm + buf * BBUF;
        #pragma unroll
        for (int ks = 0; ks < 4; ++ks) {
            uint32_t af[MI][4], bf[NATOM][2];
            const uint32_t qa = (uint32_t)(((aQ + 2 * ks) ^ swl) << 4);
            const uint32_t qb = (uint32_t)(((bQ + 2 * ks) ^ swl) << 4);
            #pragma unroll
            for (int i = 0; i < MI; ++i)
                ldmx4(af[i], Ab + i * 2048 + qa);
            #pragma unroll
            for (int jj = 0; jj < NATOM / 2; ++jj)
                ldmx4(&bf[2 * jj][0], Bb + jj * 2048 + qb);   // 16 rows (2 n-atoms) per ldmx4
            #pragma unroll
            for (int i = 0; i < MI; ++i)
                #pragma unroll
                for (int j = 0; j < NATOM; ++j)
                    mma_f16(acc[i][j], af[i], bf[j]);
        }
    };

    if (NS == 2) {
        issue(0);
        for (int c = 0; c < NC; ++c) {
            cpa_wait0();
            __syncthreads();
            if (c + 1 < NC) issue(c + 1);
            compute(c);
        }
    } else {
        issue(0);
        issue(1);
        for (int c = 0; c < NC; ++c) {
            if (c + 1 < NC) cpa_wait1(); else cpa_wait0();
            __syncthreads();
            if (c + 2 < NC) issue(c + 2);
            compute(c);
        }
    }

    __syncthreads();

    #pragma unroll
    for (int i = 0; i < MI; ++i) {
        const int r0 = bm + wm + i * 16 + gid;
        #pragma unroll
        for (int j = 0; j < NATOM; ++j) {
            const int col = bn + wn + j * 8 + tig * 2;
            if (col >= N) continue;
            float v[4];
            #pragma unroll
            for (int q = 0; q < 4; ++q) v[q] = acc[i][j][q];
            if (EPI == 2) {
                const float bb0 = bias[col], bb1 = bias[col + 1];
                v[0] += bb0; v[1] += bb1; v[2] += bb0; v[3] += bb1;
                #pragma unroll
                for (int q = 0; q < 4; ++q)
                    v[q] = (v[q] > 20.0f) ? v[q] : log1pf(__expf(v[q]));
                *(float2*)(Cout + (size_t)r0 * ldc + col)       = make_float2(v[0], v[1]);
                *(float2*)(Cout + (size_t)(r0 + 8) * ldc + col) = make_float2(v[2], v[3]);
            } else if (EPI == 4) {
                if (col < DM) {
                    *(__half2*)(Hx + (size_t)r0 * ldc + col)       = __floats2half2_rn(v[0], v[1]);
                    *(__half2*)(Hx + (size_t)(r0 + 8) * ldc + col) = __floats2half2_rn(v[2], v[3]);
                } else {
                    #pragma unroll
                    for (int q = 0; q < 4; ++q) v[q] = v[q] / (1.0f + __expf(-v[q]));
                    const int cc = col - DM;
                    *(float2*)(C2 + (size_t)r0 * ldc + cc)       = make_float2(v[0], v[1]);
                    *(float2*)(C2 + (size_t)(r0 + 8) * ldc + cc) = make_float2(v[2], v[3]);
                }
            } else {
                *(float2*)(Cout + (size_t)r0 * ldc + col)       = make_float2(v[0], v[1]);
                *(float2*)(Cout + (size_t)(r0 + 8) * ldc + col) = make_float2(v[2], v[3]);
            }
        }
    }
}

// ---------------- split-K reduce (proj): g_projp[8] -> g_proj + g_projh ----------------
__global__ void proj_reduce()
{
    const int i = blockIdx.x * blockDim.x + threadIdx.x;
    if (i >= BL * NPROJ) return;
    float s = 0.0f;
    #pragma unroll
    for (int z = 0; z < KSPLIT; ++z) s += g_projp[(size_t)z * BL * NPROJ + i];
    g_proj[i]  = s;
    g_projh[i] = __float2half(s);
}

// ---------------- one-shot prep ----------------
__device__ __forceinline__ void tr_body(const float* in, __half* out, int R, int Ccols,
                                        int rb, int cb, int tx, int ty)
{
    __shared__ float t[32][33];
    const int r0 = rb * 32, c0 = cb * 32;
    #pragma unroll
    for (int dy = 0; dy < 32; dy += 8) {
        const int r = r0 + ty + dy, c = c0 + tx;
        if (r < R && c < Ccols) t[ty + dy][tx] = in[(size_t)r * Ccols + c];
    }
    __syncthreads();
    #pragma unroll
    for (int dy = 0; dy < 32; dy += 8) {
        const int rr = c0 + ty + dy, cc = r0 + tx;
        if (rr < Ccols && cc < R)
            out[(size_t)rr * R + cc] = __float2half(t[tx][ty + dy]);
    }
}

// grid (64, 32, 5)
__global__ void prep(const float* __restrict__ W_in, const float* __restrict__ W_res,
                     const float* __restrict__ W_out, const float* __restrict__ WB,
                     const float* __restrict__ WC, const float* __restrict__ Wdt,
                     const float* __restrict__ dtw, const float* __restrict__ x_in)
{
    const int tx = threadIdx.x, ty = threadIdx.y;
    const int bx = blockIdx.x, by = blockIdx.y;
    switch (blockIdx.z) {
        case 0:  // W_in (DIN x DM): rb = by (<32), cb = bx (<64)
            tr_body(W_in, g_Wth_inres, DIN, DM, by, bx, tx, ty);
            return;
        case 1:  // W_res
            tr_body(W_res, g_Wth_inres + DM * DIN, DIN, DM, by, bx, tx, ty);
            return;
        case 2:  // W_out (DM x DIN): rb = bx (<64), cb = by (<32)
            tr_body(W_out, g_Wth_out, DM, DIN, bx, by, tx, ty);
            return;
        case 3: {  // small weights: job-indexed
            const int job = by * 64 + bx;          // 0..2047
            if (job < 64)        tr_body(WB,  g_Wth_cat,               DM, DS, job, 0, tx, ty);
            else if (job < 128)  tr_body(WC,  g_Wth_cat + DS * DM,     DM, DS, job - 64, 0, tx, ty);
            else if (job < 384) { const int t = job - 128;
                                 tr_body(Wdt, g_Wth_cat + 2 * DS * DM, DM, DR, t >> 2, t & 3, tx, ty); }
            else if (job < 640) { const int t = job - 384;
                                 tr_body(dtw, g_Wth_dtw,               DR, DM, t & 3, t >> 2, tx, ty); }
            return;
        }
        default: {  // x_in -> fp16
            const int tid = ty * 32 + tx;
            const int bid = by * 64 + bx;
            const int i = bid * 256 + tid;
            if (i < BL * DIN / 4) {
                float4 v = *(const float4*)(x_in + (size_t)i * 4);
                *(__half2*)(g_xh + (size_t)i * 4)     = __floats2half2_rn(v.x, v.y);
                *(__half2*)(g_xh + (size_t)i * 4 + 2) = __floats2half2_rn(v.z, v.w);
            }
            return;
        }
    }
}

// ---------------- causal depthwise conv + SiLU (fp16 input) ----------------
__global__ void conv_silu_kernel(const float* __restrict__ cw, const float* __restrict__ cb)
{
    const int idx = blockIdx.x * blockDim.x + threadIdx.x;
    if (idx >= BL * DM) return;
    const int d  = idx % DM;
    const int bl = idx / DM;
    const int l  = bl % L_;

    float v = cb[d];
    #pragma unroll
    for (int i = 0; i < KCONV; i++) {
        const int li = l - (KCONV - 1) + i;
        if (li >= 0)
            v = fmaf(__half2float(g_xm_h[idx + (li - l) * DM]), cw[d * KCONV + i], v);
    }
    v = v / (1.0f + __expf(-v));
    g_xc[idx]  = v;
    g_xch[idx] = __float2half(v);
}

// ---------------- selective scan: smem-tiled, cp.async double-buffered ----------------
#define ST 64
__global__ __launch_bounds__(256) void scan_kernel(
    const float* __restrict__ A_log, const float* __restrict__ Dp)
{
    __shared__ float  sd[2][ST][16];
    __shared__ float  sx[2][ST][16];
    __shared__ float  sr[2][ST][16];
    __shared__ float  sp[2][ST][32];
    __shared__ __half sy[ST][16];

    const int tid = threadIdx.x;
    const int g = tid >> 4, n = tid & 15;
    const int b  = blockIdx.x / (DM / 16);
    const int d0 = (blockIdx.x % (DM / 16)) * 16;
    const int d  = d0 + g;

    const float a  = -__expf(A_log[d * DS + n]);
    const float Dd = Dp[d];

    const float* baseD = g_delta + (size_t)b * L_ * DM + d0;
    const float* baseX = g_xc    + (size_t)b * L_ * DM + d0;
    const float* baseR = g_res   + (size_t)b * L_ * DM + d0;
    const float* baseP = g_proj  + (size_t)b * L_ * NPROJ;
    __half*      baseY = g_yh    + (size_t)b * L_ * DM + d0;

    const int t4 = tid >> 2, q4 = tid & 3;
    const int t8 = tid >> 3, q8 = tid & 7;

    uint32_t aD = (uint32_t)__cvta_generic_to_shared(&sd[0][t4][q4 * 4]);
    uint32_t aX = (uint32_t)__cvta_generic_to_shared(&sx[0][t4][q4 * 4]);
    uint32_t aR = (uint32_t)__cvta_generic_to_shared(&sr[0][t4][q4 * 4]);
    uint32_t aP0 = (uint32_t)__cvta_generic_to_shared(&sp[0][t8][q8 * 4]);
    uint32_t aP1 = (uint32_t)__cvta_generic_to_shared(&sp[0][t8 + 32][q8 * 4]);
    const uint32_t bD = sizeof(float) * ST * 16;
    const uint32_t bP = sizeof(float) * ST * 32;

    auto stage = [&](int l0, int buf) {
        cpa16(aD + buf * bD, baseD + (size_t)(l0 + t4) * DM + q4 * 4);
        cpa16(aX + buf * bD, baseX + (size_t)(l0 + t4) * DM + q4 * 4);
        cpa16(aR + buf * bD, baseR + (size_t)(l0 + t4) * DM + q4 * 4);
        cpa16(aP0 + buf * bP, baseP + (size_t)(l0 + t8) * NPROJ + q8 * 4);
        cpa16(aP1 + buf * bP, baseP + (size_t)(l0 + t8 + 32) * NPROJ + q8 * 4);
        cpa_commit();
    };

    stage(0, 0);
    cpa_wait0();
    __syncthreads();

    float h = 0.0f;
    const int NT2 = L_ / ST;
    for (int tt = 0; tt < NT2; ++tt) {
        const int buf = tt & 1;
        if (tt + 1 < NT2) stage((tt + 1) * ST, buf ^ 1);

        #pragma unroll 4
        for (int t = 0; t < ST; ++t) {
            const float dlt = sd[buf][t][g];
            const float xv  = sx[buf][t][g];
            const float bv  = sp[buf][t][n];
            const float cv  = sp[buf][t][16 + n];

            const float dA = __expf(dlt * a);
            h = fmaf(dA, h, dlt * bv * xv);

            float py = h * cv;
            py += __shfl_xor_sync(0xffffffffu, py, 8);
            py += __shfl_xor_sync(0xffffffffu, py, 4);
            py += __shfl_xor_sync(0xffffffffu, py, 2);
            py += __shfl_xor_sync(0xffffffffu, py, 1);

            if (n == 0) {
                const float sil = sr[buf][t][g];
                sy[t][g] = __float2half((py + Dd * xv) * sil);
            }
        }
        cpa_wait0();
        __syncthreads();
        if (tid < 128) {
            const int row = tid >> 1, q = tid & 1;
            float4 v = *(float4*)(&sy[row][q * 8]);
            *(float4*)(baseY + (size_t)(tt * ST + row) * DM + q * 8) = v;
        }
        __syncthreads();
    }
}

// ---------------- launch ----------------
extern "C" void kernel_launch(void* const* d_in, const int* in_sizes, int n_in,
                              void* d_out, int out_size)
{
    const float* x_in   = (const float*)d_in[0];
    const float* W_in   = (const float*)d_in[1];
    const float* W_res  = (const float*)d_in[2];
    const float* W_out  = (const float*)d_in[3];
    const float* conv_w = (const float*)d_in[4];
    const float* conv_b = (const float*)d_in[5];
    const float* A_log  = (const float*)d_in[6];
    const float* Dvec   = (const float*)d_in[7];
    const float* W_B    = (const float*)d_in[8];
    const float* W_C    = (const float*)d_in[9];
    const float* W_dt   = (const float*)d_in[10];
    const float* dt_w   = (const float*)d_in[11];
    const float* dt_b   = (const float*)d_in[12];
    float* out = (float*)d_out;

    float  *pres, *pprojp, *pdelta;
    __half *pxh, *pxmh, *pxch, *pprojh, *pyh, *pWir, *pWto, *pWtc, *pWtd;
    cudaGetSymbolAddress((void**)&pres,   g_res);
    cudaGetSymbolAddress((void**)&pprojp, g_projp);
    cudaGetSymbolAddress((void**)&pdelta, g_delta);
    cudaGetSymbolAddress((void**)&pxh,    g_xh);
    cudaGetSymbolAddress((void**)&pxmh,   g_xm_h);
    cudaGetSymbolAddress((void**)&pxch,   g_xch);
    cudaGetSymbolAddress((void**)&pprojh, g_projh);
    cudaGetSymbolAddress((void**)&pyh,    g_yh);
    cudaGetSymbolAddress((void**)&pWir,   g_Wth_inres);
    cudaGetSymbolAddress((void**)&pWto,   g_Wth_out);
    cudaGetSymbolAddress((void**)&pWtc,   g_Wth_cat);
    cudaGetSymbolAddress((void**)&pWtd,   g_Wth_dtw);

    const int smem128 = 3 * (128 * 128 + 128 * 128);   // 98304 (MT=128, 3-stage)
    const int smem64  = 3 * (64 * 128 + 128 * 128);    // 73728 (MT=64, 3-stage)
    cudaFuncSetAttribute((const void*)gemm_h<128, 128, 3, 4>, cudaFuncAttributeMaxDynamicSharedMemorySize, smem128);
    cudaFuncSetAttribute((const void*)gemm_h<128, 128, 3, 0>, cudaFuncAttributeMaxDynamicSharedMemorySize, smem128);
    cudaFuncSetAttribute((const void*)gemm_h<64, 128, 3, 2>,  cudaFuncAttributeMaxDynamicSharedMemorySize, smem64);
    cudaFuncSetAttribute((const void*)gemm_h<64, 128, 3, 0>,  cudaFuncAttributeMaxDynamicSharedMemorySize, smem64);

    // 0: all prep in one kernel (right-sized grid)
    prep<<<dim3(64, 32, 5), dim3(32, 8)>>>(W_in, W_res, W_out, W_B, W_C, W_dt, dt_w, x_in);

    // 1: fused in+res projection (N=4096): R9 champion tile MT=128 (512 CTAs)
    gemm_h<128, 128, 3, 4><<<dim3(32, 16), 256, smem128>>>(
        pxh, DIN, pWir, nullptr, pres, pxmh, DM, nullptr, 2 * DM, DIN, 1, 0);

    // 2: conv + silu
    conv_silu_kernel<<<(BL * DM + 255) / 256, 256>>>(conv_w, conv_b);

    // 3: fused skinny projections (N=160), split-K x8 (256 CTAs)
    gemm_h<128, 128, 3, 0><<<dim3(2, 16, KSPLIT), 256, smem128>>>(
        pxch, DM, pWtc, pprojp, nullptr, nullptr, NPROJ, nullptr, NPROJ, DM,
        KSPLIT, (size_t)BL * NPROJ);

    // 4: reduce proj partials
    proj_reduce<<<(BL * NPROJ + 255) / 256, 256>>>();

    // 5: delta = softplus(dtr @ dt_w + dt_b) (512 CTAs)
    gemm_h<64, 128, 3, 2><<<dim3(16, 32), 256, smem64>>>(
        pprojh + 2 * DS, NPROJ, pWtd, pdelta, nullptr, nullptr, DM, dt_b, DM, DR, 1, 0);

    // 6: selective scan
    scan_kernel<<<B_ * DM / 16, 256>>>(A_log, Dvec);

    // 7: output projection (N=1024) (256 CTAs, direct)
    gemm_h<64, 128, 3, 0><<<dim3(8, 32), 256, smem64>>>(
        pyh, DM, pWto, out, nullptr, nullptr, DIN, nullptr, DIN, DM, 1, 0);
}

// round 17
// speedup vs baseline: 1.0241x; 1.0241x over previous
#include <cuda_runtime.h>
#include <cuda_fp16.h>
#include <math.h>
#include <stdint.h>

#define B_    2
#define L_    1024
#define DIN   1024
#define DM    2048
#define DS    16
#define DR    128
#define KCONV 4
#define BL    (B_ * L_)
#define NPROJ 160
#define KSPLIT 8

// ---------------- scratch ----------------
__device__ __half g_xh[BL * DIN];            // fp16 x_in
__device__ __half g_xm_h[BL * DM];           // fp16 x = x_in @ W_in (conv input)
__device__ float  g_res[BL * DM];            // fp32 silu(x_in @ W_res)
__device__ float  g_xc[BL * DM];             // fp32 silu(conv(x)) (scan)
__device__ __half g_xch[BL * DM];            // fp16 copy (GEMM A)
__device__ float  g_projp[KSPLIT * BL * NPROJ];
__device__ float  g_proj[BL * NPROJ];
__device__ __half g_projh[BL * NPROJ];
__device__ float  g_delta[BL * DM];
__device__ __half g_yh[BL * DM];
__device__ __half g_Wth_inres[2 * DM * DIN];
__device__ __half g_Wth_out[DIN * DM];
__device__ __half g_Wth_cat[NPROJ * DM];
__device__ __half g_Wth_dtw[DM * DR];

// ---------------- helpers ----------------
__device__ __forceinline__ void mma_f16(float* c, const uint32_t* a, const uint32_t* b) {
    asm volatile(
        "mma.sync.aligned.m16n8k16.row.col.f32.f16.f16.f32 "
        "{%0,%1,%2,%3}, {%4,%5,%6,%7}, {%8,%9}, {%0,%1,%2,%3};"
        : "+f"(c[0]), "+f"(c[1]), "+f"(c[2]), "+f"(c[3])
        : "r"(a[0]), "r"(a[1]), "r"(a[2]), "r"(a[3]), "r"(b[0]), "r"(b[1]));
}
__device__ __forceinline__ void ldmx4(uint32_t* r, uint32_t addr) {
    asm volatile("ldmatrix.sync.aligned.m8n8.x4.shared.b16 {%0,%1,%2,%3}, [%4];"
        : "=r"(r[0]), "=r"(r[1]), "=r"(r[2]), "=r"(r[3]) : "r"(addr));
}
__device__ __forceinline__ void cpa16(uint32_t dst, const void* src) {
    asm volatile("cp.async.cg.shared.global [%0], [%1], 16;" :: "r"(dst), "l"(src));
}
__device__ __forceinline__ void cpa16z(uint32_t dst, const void* src, int srcbytes) {
    asm volatile("cp.async.cg.shared.global [%0], [%1], 16, %2;"
                 :: "r"(dst), "l"(src), "r"(srcbytes));
}
__device__ __forceinline__ void cpa_commit() { asm volatile("cp.async.commit_group;"); }
__device__ __forceinline__ void cpa_wait1()  { asm volatile("cp.async.wait_group 1;" ::: "memory"); }
__device__ __forceinline__ void cpa_wait0()  { asm volatile("cp.async.wait_group 0;" ::: "memory"); }

// ============ fp16 mma GEMM: MTx128 CTA tile, BK=64, 3-stage cp.async, ldmatrix ========
// C(M x N) = A(M x K) @ Bt(N x K)^T. Split-K via gridDim.z (kdiv slices, partials at
// C + z*pstride). MT in {64,128}. SMEM rows: 128B, SW128 swizzle quad ^ (row&7).
// EPI: 0=plain fp32, 2=softplus(+bias) fp32, 4=dual: col<DM -> fp16 Hx, col>=DM -> silu fp32 C2
template<int MT, int EPI>
__global__ void __launch_bounds__(256, 2) gemm_h(
    const __half* __restrict__ A, int lda,
    const __half* __restrict__ Bt,
    float* __restrict__ C, float* __restrict__ C2, __half* __restrict__ Hx, int ldc,
    const float* __restrict__ bias, int N, int K,
    int kdiv, size_t pstride)
{
    constexpr int ABUF = MT * 128;        // bytes per A stage (128B rows)
    constexpr int BBUF = 128 * 128;       // bytes per B stage
    constexpr int MI   = MT / 32;         // m-atoms per warp tile
    extern __shared__ char sh[];
    const uint32_t sA = (uint32_t)__cvta_generic_to_shared(sh);
    const uint32_t sB = sA + 3 * ABUF;

    const int tid  = threadIdx.x;
    const int wid  = tid >> 5, lane = tid & 31;
    const int gid  = lane >> 2, tig = lane & 3;
    const int bm   = blockIdx.y * MT, bn = blockIdx.x * 128;
    const int wm   = (wid >> 2) * (MT / 2);
    const int wn   = (wid & 3) * 32;

    const int Keff = K / kdiv;
    const int koff = blockIdx.z * Keff;
    float* Cout = C + (size_t)blockIdx.z * pstride;

    float acc[MI][4][4] = {};

    const int NC = Keff >> 6;             // 64-wide K chunks

    auto issue = [&](int c) {
        const int buf = c % 3;
        const int ko  = koff + c * 64;
        #pragma unroll
        for (int it = 0; it < MT * 8 / 256; ++it) {
            const int i = tid + it * 256;
            const int row = i >> 3, q = i & 7;
            const int sw = q ^ (row & 7);
            cpa16(sA + buf * ABUF + (uint32_t)(row * 128 + sw * 16),
                  A + (size_t)(bm + row) * lda + ko + q * 8);
        }
        #pragma unroll
        for (int it = 0; it < 4; ++it) {
            const int i = tid + it * 256;
            const int row = i >> 3, q = i & 7;
            const int sw = q ^ (row & 7);
            const int brow = bn + row;
            cpa16z(sB + buf * BBUF + (uint32_t)(row * 128 + sw * 16),
                   Bt + (size_t)brow * K + ko + q * 8,
                   (brow < N) ? 16 : 0);
        }
        cpa_commit();
    };

    const int swl = lane & 7;
    const uint32_t aLm = sA + (uint32_t)((wm + (lane & 15)) * 128);
    const int aQ = lane >> 4;
    const uint32_t bLm = sB + (uint32_t)((wn + (lane & 7) + ((lane >> 4) & 1) * 8) * 128);
    const int bQ = (lane >> 3) & 1;

    issue(0);
    issue(1);

    for (int c = 0; c < NC; ++c) {
        if (c + 1 < NC) cpa_wait1(); else cpa_wait0();
        __syncthreads();
        if (c + 2 < NC) issue(c + 2);

        const int buf = c % 3;
        const uint32_t Ab = aLm + buf * ABUF;
        const uint32_t Bb = bLm + buf * BBUF;
        #pragma unroll
        for (int ks = 0; ks < 4; ++ks) {
            uint32_t af[MI][4], bf[4][2];
            const uint32_t qa = (uint32_t)(((aQ + 2 * ks) ^ swl) << 4);
            const uint32_t qb = (uint32_t)(((bQ + 2 * ks) ^ swl) << 4);
            #pragma unroll
            for (int i = 0; i < MI; ++i)
                ldmx4(af[i], Ab + i * 2048 + qa);
            #pragma unroll
            for (int jj = 0; jj < 2; ++jj)
                ldmx4(&bf[2 * jj][0], Bb + jj * 2048 + qb);
            #pragma unroll
            for (int i = 0; i < MI; ++i)
                #pragma unroll
                for (int j = 0; j < 4; ++j)
                    mma_f16(acc[i][j], af[i], bf[j]);
        }
    }

    __syncthreads();

    #pragma unroll
    for (int i = 0; i < MI; ++i) {
        const int r0 = bm + wm + i * 16 + gid;
        #pragma unroll
        for (int j = 0; j < 4; ++j) {
            const int col = bn + wn + j * 8 + tig * 2;
            if (col >= N) continue;
            float v[4];
            #pragma unroll
            for (int q = 0; q < 4; ++q) v[q] = acc[i][j][q];
            if (EPI == 2) {
                const float bb0 = bias[col], bb1 = bias[col + 1];
                v[0] += bb0; v[1] += bb1; v[2] += bb0; v[3] += bb1;
                #pragma unroll
                for (int q = 0; q < 4; ++q)
                    v[q] = (v[q] > 20.0f) ? v[q] : log1pf(__expf(v[q]));
                *(float2*)(Cout + (size_t)r0 * ldc + col)       = make_float2(v[0], v[1]);
                *(float2*)(Cout + (size_t)(r0 + 8) * ldc + col) = make_float2(v[2], v[3]);
            } else if (EPI == 4) {
                if (col < DM) {
                    *(__half2*)(Hx + (size_t)r0 * ldc + col)       = __floats2half2_rn(v[0], v[1]);
                    *(__half2*)(Hx + (size_t)(r0 + 8) * ldc + col) = __floats2half2_rn(v[2], v[3]);
                } else {
                    #pragma unroll
                    for (int q = 0; q < 4; ++q) v[q] = v[q] / (1.0f + __expf(-v[q]));
                    const int cc = col - DM;
                    *(float2*)(C2 + (size_t)r0 * ldc + cc)       = make_float2(v[0], v[1]);
                    *(float2*)(C2 + (size_t)(r0 + 8) * ldc + cc) = make_float2(v[2], v[3]);
                }
            } else {
                *(float2*)(Cout + (size_t)r0 * ldc + col)       = make_float2(v[0], v[1]);
                *(float2*)(Cout + (size_t)(r0 + 8) * ldc + col) = make_float2(v[2], v[3]);
            }
        }
    }
}

// ---------------- split-K reduce ----------------
__global__ void proj_reduce()
{
    const int i = blockIdx.x * blockDim.x + threadIdx.x;
    if (i >= BL * NPROJ) return;
    float s = 0.0f;
    #pragma unroll
    for (int z = 0; z < KSPLIT; ++z) s += g_projp[(size_t)z * BL * NPROJ + i];
    g_proj[i]  = s;
    g_projh[i] = __float2half(s);
}

// ---------------- one-shot prep ----------------
__device__ __forceinline__ void tr_body(const float* in, __half* out, int R, int Ccols,
                                        int rb, int cb, int tx, int ty)
{
    __shared__ float t[32][33];
    const int r0 = rb * 32, c0 = cb * 32;
    #pragma unroll
    for (int dy = 0; dy < 32; dy += 8) {
        const int r = r0 + ty + dy, c = c0 + tx;
        if (r < R && c < Ccols) t[ty + dy][tx] = in[(size_t)r * Ccols + c];
    }
    __syncthreads();
    #pragma unroll
    for (int dy = 0; dy < 32; dy += 8) {
        const int rr = c0 + ty + dy, cc = r0 + tx;
        if (rr < Ccols && cc < R)
            out[(size_t)rr * R + cc] = __float2half(t[tx][ty + dy]);
    }
}

__global__ void prep(const float* __restrict__ W_in, const float* __restrict__ W_res,
                     const float* __restrict__ W_out, const float* __restrict__ WB,
                     const float* __restrict__ WC, const float* __restrict__ Wdt,
                     const float* __restrict__ dtw, const float* __restrict__ x_in)
{
    const int tx = threadIdx.x, ty = threadIdx.y;
    const int bx = blockIdx.x, by = blockIdx.y;
    switch (blockIdx.z) {
        case 0:
            if (by < DIN / 32) tr_body(W_in, g_Wth_inres, DIN, DM, by, bx, tx, ty);
            return;
        case 1:
            if (by < DIN / 32) tr_body(W_res, g_Wth_inres + DM * DIN, DIN, DM, by, bx, tx, ty);
            return;
        case 2:
            if (bx < DIN / 32) tr_body(W_out, g_Wth_out, DM, DIN, by, bx, tx, ty);
            return;
        case 3:
            if (bx == 0)            tr_body(WB,  g_Wth_cat,               DM, DS, by, 0, tx, ty);
            else if (bx == 1)       tr_body(WC,  g_Wth_cat + DS * DM,     DM, DS, by, 0, tx, ty);
            else if (bx < 6)        tr_body(Wdt, g_Wth_cat + 2 * DS * DM, DM, DR, by, bx - 2, tx, ty);
            else if (bx < 10 && bx - 6 < DR / 32)
                                    tr_body(dtw, g_Wth_dtw,               DR, DM, bx - 6, by, tx, ty);
            return;
        default: {
            const int tid = ty * 32 + tx;
            const int bid = by * gridDim.x + bx;
            const int i = bid * 256 + tid;
            if (i < BL * DIN / 4) {
                float4 v = *(const float4*)(x_in + (size_t)i * 4);
                *(__half2*)(g_xh + (size_t)i * 4)     = __floats2half2_rn(v.x, v.y);
                *(__half2*)(g_xh + (size_t)i * 4 + 2) = __floats2half2_rn(v.z, v.w);
            }
            return;
        }
    }
}

// ---------------- causal depthwise conv + SiLU (fp16 input) ----------------
__global__ void conv_silu_kernel(const float* __restrict__ cw, const float* __restrict__ cb)
{
    const int idx = blockIdx.x * blockDim.x + threadIdx.x;
    if (idx >= BL * DM) return;
    const int d  = idx % DM;
    const int bl = idx / DM;
    const int l  = bl % L_;

    float v = cb[d];
    #pragma unroll
    for (int i = 0; i < KCONV; i++) {
        const int li = l - (KCONV - 1) + i;
        if (li >= 0)
            v = fmaf(__half2float(g_xm_h[idx + (li - l) * DM]), cw[d * KCONV + i], v);
    }
    v = v / (1.0f + __expf(-v));
    g_xc[idx]  = v;
    g_xch[idx] = __float2half(v);
}

// ---------------- selective scan ----------------
#define ST 64
__global__ __launch_bounds__(256) void scan_kernel(
    const float* __restrict__ A_log, const float* __restrict__ Dp)
{
    __shared__ float  sd[2][ST][16];
    __shared__ float  sx[2][ST][16];
    __shared__ float  sr[2][ST][16];
    __shared__ float  sp[2][ST][32];
    __shared__ __half sy[ST][16];

    const int tid = threadIdx.x;
    const int g = tid >> 4, n = tid & 15;
    const int b  = blockIdx.x / (DM / 16);
    const int d0 = (blockIdx.x % (DM / 16)) * 16;
    const int d  = d0 + g;

    const float a  = -__expf(A_log[d * DS + n]);
    const float Dd = Dp[d];

    const float* baseD = g_delta + (size_t)b * L_ * DM + d0;
    const float* baseX = g_xc    + (size_t)b * L_ * DM + d0;
    const float* baseR = g_res   + (size_t)b * L_ * DM + d0;
    const float* baseP = g_proj  + (size_t)b * L_ * NPROJ;
    __half*      baseY = g_yh    + (size_t)b * L_ * DM + d0;

    const int t4 = tid >> 2, q4 = tid & 3;
    const int t8 = tid >> 3, q8 = tid & 7;

    uint32_t aD = (uint32_t)__cvta_generic_to_shared(&sd[0][t4][q4 * 4]);
    uint32_t aX = (uint32_t)__cvta_generic_to_shared(&sx[0][t4][q4 * 4]);
    uint32_t aR = (uint32_t)__cvta_generic_to_shared(&sr[0][t4][q4 * 4]);
    uint32_t aP0 = (uint32_t)__cvta_generic_to_shared(&sp[0][t8][q8 * 4]);
    uint32_t aP1 = (uint32_t)__cvta_generic_to_shared(&sp[0][t8 + 32][q8 * 4]);
    const uint32_t bD = sizeof(float) * ST * 16;
    const uint32_t bP = sizeof(float) * ST * 32;

    auto stage = [&](int l0, int buf) {
        cpa16(aD + buf * bD, baseD + (size_t)(l0 + t4) * DM + q4 * 4);
        cpa16(aX + buf * bD, baseX + (size_t)(l0 + t4) * DM + q4 * 4);
        cpa16(aR + buf * bD, baseR + (size_t)(l0 + t4) * DM + q4 * 4);
        cpa16(aP0 + buf * bP, baseP + (size_t)(l0 + t8) * NPROJ + q8 * 4);
        cpa16(aP1 + buf * bP, baseP + (size_t)(l0 + t8 + 32) * NPROJ + q8 * 4);
        cpa_commit();
    };

    stage(0, 0);
    cpa_wait0();
    __syncthreads();

    float h = 0.0f;
    const int NT = L_ / ST;
    for (int tt = 0; tt < NT; ++tt) {
        const int buf = tt & 1;
        if (tt + 1 < NT) stage((tt + 1) * ST, buf ^ 1);

        #pragma unroll 4
        for (int t = 0; t < ST; ++t) {
            const float dlt = sd[buf][t][g];
            const float xv  = sx[buf][t][g];
            const float bv  = sp[buf][t][n];
            const float cv  = sp[buf][t][16 + n];

            const float dA = __expf(dlt * a);
            h = fmaf(dA, h, dlt * bv * xv);

            float py = h * cv;
            py += __shfl_xor_sync(0xffffffffu, py, 8);
            py += __shfl_xor_sync(0xffffffffu, py, 4);
            py += __shfl_xor_sync(0xffffffffu, py, 2);
            py += __shfl_xor_sync(0xffffffffu, py, 1);

            if (n == 0) {
                const float sil = sr[buf][t][g];
                sy[t][g] = __float2half((py + Dd * xv) * sil);
            }
        }
        cpa_wait0();
        __syncthreads();
        if (tid < 128) {
            const int row = tid >> 1, q = tid & 1;
            float4 v = *(float4*)(&sy[row][q * 8]);
            *(float4*)(baseY + (size_t)(tt * ST + row) * DM + q * 8) = v;
        }
        __syncthreads();
    }
}

// ---------------- launch ----------------
extern "C" void kernel_launch(void* const* d_in, const int* in_sizes, int n_in,
                              void* d_out, int out_size)
{
    const float* x_in   = (const float*)d_in[0];
    const float* W_in   = (const float*)d_in[1];
    const float* W_res  = (const float*)d_in[2];
    const float* W_out  = (const float*)d_in[3];
    const float* conv_w = (const float*)d_in[4];
    const float* conv_b = (const float*)d_in[5];
    const float* A_log  = (const float*)d_in[6];
    const float* Dvec   = (const float*)d_in[7];
    const float* W_B    = (const float*)d_in[8];
    const float* W_C    = (const float*)d_in[9];
    const float* W_dt   = (const float*)d_in[10];
    const float* dt_w   = (const float*)d_in[11];
    const float* dt_b   = (const float*)d_in[12];
    float* out = (float*)d_out;

    float  *pres, *pprojp, *pdelta;
    __half *pxh, *pxmh, *pxch, *pprojh, *pyh, *pWir, *pWto, *pWtc, *pWtd;
    cudaGetSymbolAddress((void**)&pres,   g_res);
    cudaGetSymbolAddress((void**)&pprojp, g_projp);
    cudaGetSymbolAddress((void**)&pdelta, g_delta);
    cudaGetSymbolAddress((void**)&pxh,    g_xh);
    cudaGetSymbolAddress((void**)&pxmh,   g_xm_h);
    cudaGetSymbolAddress((void**)&pxch,   g_xch);
    cudaGetSymbolAddress((void**)&pprojh, g_projh);
    cudaGetSymbolAddress((void**)&pyh,    g_yh);
    cudaGetSymbolAddress((void**)&pWir,   g_Wth_inres);
    cudaGetSymbolAddress((void**)&pWto,   g_Wth_out);
    cudaGetSymbolAddress((void**)&pWtc,   g_Wth_cat);
    cudaGetSymbolAddress((void**)&pWtd,   g_Wth_dtw);

    const int smem128 = 3 * (128 * 128 + 128 * 128);   // 98304
    const int smem64  = 3 * (64 * 128 + 128 * 128);    // 73728
    cudaFuncSetAttribute(gemm_h<128, 4>, cudaFuncAttributeMaxDynamicSharedMemorySize, smem128);
    cudaFuncSetAttribute(gemm_h<128, 0>, cudaFuncAttributeMaxDynamicSharedMemorySize, smem128);
    cudaFuncSetAttribute(gemm_h<64, 2>,  cudaFuncAttributeMaxDynamicSharedMemorySize, smem64);
    cudaFuncSetAttribute(gemm_h<64, 0>,  cudaFuncAttributeMaxDynamicSharedMemorySize, smem64);

    // 0: all prep in one kernel
    prep<<<dim3(64, 64, 5), dim3(32, 8)>>>(W_in, W_res, W_out, W_B, W_C, W_dt, dt_w, x_in);

    // 1: fused in+res projection (N=4096): x -> fp16 xm, res -> silu fp32  (512 CTAs)
    gemm_h<128, 4><<<dim3(32, 16), 256, smem128>>>(
        pxh, DIN, pWir, nullptr, pres, pxmh, DM, nullptr, 2 * DM, DIN, 1, 0);

    // 2: conv + silu
    conv_silu_kernel<<<(BL * DM + 255) / 256, 256>>>(conv_w, conv_b);

    // 3: fused skinny projections (N=160), split-K x8 (256 CTAs)
    gemm_h<128, 0><<<dim3(2, 16, KSPLIT), 256, smem128>>>(
        pxch, DM, pWtc, pprojp, nullptr, nullptr, NPROJ, nullptr, NPROJ, DM,
        KSPLIT, (size_t)BL * NPROJ);

    // 4: reduce partials
    proj_reduce<<<(BL * NPROJ + 255) / 256, 256>>>();

    // 5: delta = softplus(dtr @ dt_w + dt_b) (512 CTAs)
    gemm_h<64, 2><<<dim3(16, 32), 256, smem64>>>(
        pprojh + 2 * DS, NPROJ, pWtd, pdelta, nullptr, nullptr, DM, dt_b, DM, DR, 1, 0);

    // 6: selective scan
    scan_kernel<<<B_ * DM / 16, 256>>>(A_log, Dvec);

    // 7: output projection (N=1024) (256 CTAs)
    gemm_h<64, 0><<<dim3(8, 32), 256, smem64>>>(
        pyh, DM, pWto, out, nullptr, nullptr, DIN, nullptr, DIN, DM, 1, 0);
}